// round 10
// baseline (speedup 1.0000x reference)
#include <cuda_runtime.h>
#include <cuda_fp16.h>
#include <math.h>
#include <stdint.h>

// Problem constants
#define B_   4
#define S_   2048
#define HID_ 2048
#define NH_  16
#define HD_  128
#define CH_  64
#define LCH_ 32
#define M1_  (B_*S_)   // 8192

// GEMM tiling (single-product fp16 mma.sync, f32 acc)
#define BM_ 128
#define BN_ 128
#define BK_ 64                     // 128 bytes per row
#define MSTG_ 32768                // 16KB A + 16KB B
#define MAIN_SMEM (3*MSTG_)        // 98304 -> 2 CTAs/SM

__device__ __forceinline__ uint32_t smem_to_u32(const void* p) {
    uint32_t a;
    asm("{ .reg .u64 t; cvta.to.shared.u64 t, %1; cvt.u32.u64 %0, t; }"
        : "=r"(a) : "l"(p));
    return a;
}
// SW128 swizzle for 128-byte rows
__device__ __forceinline__ uint32_t swz128(uint32_t b) { return b ^ ((b >> 3) & 0x70); }

#define CP_ASYNC16(sa, ga) \
    asm volatile("cp.async.cg.shared.global [%0], [%1], 16;" :: "r"((uint32_t)(sa)), "l"(ga))
#define CP_COMMIT() asm volatile("cp.async.commit_group;" ::: "memory")
#define CP_WAIT1()  asm volatile("cp.async.wait_group 1;" ::: "memory")

#define LDSM4(r, addr) \
    asm volatile("ldmatrix.sync.aligned.m8n8.x4.shared.b16 {%0,%1,%2,%3}, [%4];" \
        : "=r"((r)[0]), "=r"((r)[1]), "=r"((r)[2]), "=r"((r)[3]) : "r"(addr))

#define MMA_F32(c, a, b0, b1) \
    asm volatile("mma.sync.aligned.m16n8k16.row.col.f32.f16.f16.f32 " \
        "{%0,%1,%2,%3}, {%4,%5,%6,%7}, {%8,%9}, {%0,%1,%2,%3};" \
        : "+f"((c)[0]), "+f"((c)[1]), "+f"((c)[2]), "+f"((c)[3]) \
        : "r"((a)[0]), "r"((a)[1]), "r"((a)[2]), "r"((a)[3]), "r"(b0), "r"(b1))

// ---------------------------------------------------------------------------
// scratch
// ---------------------------------------------------------------------------
__device__ __half g_qkv[(size_t)M1_ * 3 * HID_];   // 96 MB fp16
__device__ __half g_xh[(size_t)M1_ * HID_];
__device__ __half g_ah[(size_t)M1_ * HID_];
__device__ __half g_wqh[(size_t)3 * HID_ * HID_];
__device__ __half g_woh[(size_t)HID_ * HID_];
__device__ float g_numloc[B_*NH_*S_];
__device__ float g_denloc[B_*NH_*S_];
__device__ float g_kvloc [B_*NH_*CH_*HD_];
__device__ float g_ksloc [B_*NH_*CH_*HD_];
__device__ float g_ckv   [B_*NH_*CH_*HD_];
__device__ float g_cks   [B_*NH_*CH_*HD_];

// ---------------------------------------------------------------------------
// conversions
// ---------------------------------------------------------------------------
__global__ void __launch_bounds__(256) to_f16(
    const float* __restrict__ in, __half* __restrict__ outp, int n4)
{
    int i = blockIdx.x * blockDim.x + threadIdx.x;
    if (i >= n4) return;
    float4 v = ((const float4*)in)[i];
    __half2 a, b;
    a.x = __float2half_rn(v.x); a.y = __float2half_rn(v.y);
    b.x = __float2half_rn(v.z); b.y = __float2half_rn(v.w);
    ((__half2*)outp)[2*i]   = a;
    ((__half2*)outp)[2*i+1] = b;
}

// W[K,N] fp32 -> T[N,K] fp16
__global__ void __launch_bounds__(256) trans_f16(
    const float* __restrict__ W, __half* __restrict__ T, int K, int N)
{
    __shared__ float tile[32][33];
    int tx = threadIdx.x, ty = threadIdx.y;
    int bx = blockIdx.x * 32;  // N
    int by = blockIdx.y * 32;  // K
    #pragma unroll
    for (int j = 0; j < 4; j++)
        tile[ty + j*8][tx] = W[(size_t)(by + ty + j*8) * N + bx + tx];
    __syncthreads();
    #pragma unroll
    for (int j = 0; j < 4; j++) {
        float v = tile[tx][ty + j*8];
        T[(size_t)(bx + ty + j*8) * K + by + tx] = __float2half_rn(v);
    }
}

// ---------------------------------------------------------------------------
// GEMM: C[M,N] = A[M,K] * B[N,K]^T  (f16 in, f32 acc), BK=64, 3-stage
// ---------------------------------------------------------------------------
__device__ __forceinline__ void load_stage_main(
    uint32_t sb, int it, int m0, int n0, int K,
    const __half* __restrict__ A, const __half* __restrict__ Bv, int tid)
{
    uint32_t stg = sb + (uint32_t)(it % 3) * MSTG_;
    const int k0 = it * BK_;
    // A: 128 rows x 128B (8 chunks); B: same at +16384
    #pragma unroll
    for (int h = 0; h < 4; h++) {
        int n = tid + h * 256;      // 0..1023
        int row = n >> 3, ch = n & 7;
        uint32_t so = swz128((uint32_t)(row * 128 + ch * 16));
        CP_ASYNC16(stg +         so, A  + (size_t)(m0 + row) * K + k0 + ch * 8);
        CP_ASYNC16(stg + 16384 + so, Bv + (size_t)(n0 + row) * K + k0 + ch * 8);
    }
}

template <typename OutT>
__global__ void __launch_bounds__(256, 2) gemm_main(
    const __half* __restrict__ Ah, const __half* __restrict__ Bh,
    OutT* __restrict__ C, int N, int K)
{
    extern __shared__ char smem[];
    uint32_t sb = smem_to_u32(smem);
    const int tid = threadIdx.x;
    const int lane = tid & 31;
    const int wid = tid >> 5;
    const int wm = wid & 1;
    const int wn = wid >> 1;

    const int m0 = blockIdx.y * BM_;
    const int n0 = blockIdx.x * BN_;
    const int nk = K / BK_;

    float acc[4][4][4];
    #pragma unroll
    for (int a = 0; a < 4; a++)
        #pragma unroll
        for (int b = 0; b < 4; b++)
            #pragma unroll
            for (int c = 0; c < 4; c++) acc[a][b][c] = 0.f;

    load_stage_main(sb, 0, m0, n0, K, Ah, Bh, tid); CP_COMMIT();
    load_stage_main(sb, 1, m0, n0, K, Ah, Bh, tid); CP_COMMIT();

    const int aRow = wm * 64 + (lane & 15);
    const int aKh  = lane >> 4;
    const int bRow = wn * 32 + (lane & 7) + ((lane >> 4) << 3);
    const int bKh  = (lane >> 3) & 1;

    for (int i = 0; i < nk; i++) {
        CP_WAIT1();
        __syncthreads();
        uint32_t stg = sb + (uint32_t)(i % 3) * MSTG_;

        #pragma unroll
        for (int ks = 0; ks < 4; ks++) {
            uint32_t ah[4][4], bh[2][4];
            #pragma unroll
            for (int mt = 0; mt < 4; mt++) {
                uint32_t off = swz128((uint32_t)((aRow + mt * 16) * 128 + (ks * 2 + aKh) * 16));
                LDSM4(ah[mt], stg + off);
            }
            #pragma unroll
            for (int ng = 0; ng < 2; ng++) {
                uint32_t off = swz128((uint32_t)((bRow + ng * 16) * 128 + (ks * 2 + bKh) * 16));
                LDSM4(bh[ng], stg + 16384 + off);
            }
            #pragma unroll
            for (int mt = 0; mt < 4; mt++)
                #pragma unroll
                for (int nt = 0; nt < 4; nt++) {
                    const int ng = nt >> 1, p2 = (nt & 1) * 2;
                    MMA_F32(acc[mt][nt], ah[mt], bh[ng][p2], bh[ng][p2 + 1]);
                }
        }
        if (i + 2 < nk)
            load_stage_main(sb, i + 2, m0, n0, K, Ah, Bh, tid);
        CP_COMMIT();
    }

    const int rb = m0 + wm * 64 + (lane >> 2);
    const int cb = n0 + wn * 32 + (lane & 3) * 2;
    #pragma unroll
    for (int mt = 0; mt < 4; mt++) {
        #pragma unroll
        for (int nt = 0; nt < 4; nt++) {
            if constexpr (sizeof(OutT) == 4) {
                float* p0 = (float*)C + (size_t)(rb + mt * 16) * N + cb + nt * 8;
                float* p1 = (float*)C + (size_t)(rb + mt * 16 + 8) * N + cb + nt * 8;
                *(float2*)p0 = make_float2(acc[mt][nt][0], acc[mt][nt][1]);
                *(float2*)p1 = make_float2(acc[mt][nt][2], acc[mt][nt][3]);
            } else {
                __half* p0 = (__half*)C + (size_t)(rb + mt * 16) * N + cb + nt * 8;
                __half* p1 = (__half*)C + (size_t)(rb + mt * 16 + 8) * N + cb + nt * 8;
                __half2 v0, v1;
                v0.x = __float2half_rn(acc[mt][nt][0]); v0.y = __float2half_rn(acc[mt][nt][1]);
                v1.x = __float2half_rn(acc[mt][nt][2]); v1.y = __float2half_rn(acc[mt][nt][3]);
                *(__half2*)p0 = v0;
                *(__half2*)p1 = v1;
            }
        }
    }
}

// ---------------------------------------------------------------------------
// scan — warp-per-(bh,chunk); qkv in fp16
// ---------------------------------------------------------------------------
__device__ __forceinline__ float phi_f(float u) { return u > 0.f ? u + 1.f : expf(u); }
__device__ __forceinline__ float sigmoid_f(float p) { return 1.f / (1.f + expf(-p)); }

__device__ __forceinline__ float4 load4h(const __half* p) {
    uint2 raw = *(const uint2*)p;
    float2 a = __half22float2(*(__half2*)&raw.x);
    float2 b = __half22float2(*(__half2*)&raw.y);
    return make_float4(a.x, a.y, b.x, b.y);
}

__device__ __forceinline__ float2 warp_red2(float a, float b) {
    #pragma unroll
    for (int off = 16; off > 0; off >>= 1) {
        a += __shfl_xor_sync(0xffffffffu, a, off);
        b += __shfl_xor_sync(0xffffffffu, b, off);
    }
    return make_float2(a, b);
}

__global__ void __launch_bounds__(128) scan_phaseA(
    const __half* __restrict__ qkv, const float* __restrict__ mask,
    const float* __restrict__ decay_p,
    float* __restrict__ num_loc, float* __restrict__ den_loc,
    float* __restrict__ kv_loc, float* __restrict__ ks_loc)
{
    const int gw = (blockIdx.x * blockDim.x + threadIdx.x) >> 5;
    const int lane = threadIdx.x & 31;
    const int c  = gw % CH_;
    const int bh = gw / CH_;
    const int h  = bh % NH_;
    const int b  = bh / NH_;
    const float decay = sigmoid_f(decay_p[h]);

    float4 kv = make_float4(0,0,0,0), ks = make_float4(0,0,0,0);
    const size_t qbase = ((size_t)(b * S_ + c * LCH_)) * (3 * HID_) + h * HD_ + lane * 4;
    const float* mrow = mask + (size_t)b * S_ + c * LCH_;

    for (int t = 0; t < LCH_; t++) {
        size_t off = qbase + (size_t)t * (3 * HID_);
        float4 q4 = load4h(qkv + off);
        float4 k4 = load4h(qkv + off + HID_);
        float4 v4 = load4h(qkv + off + 2 * HID_);
        float m = mrow[t];
        float4 qp = make_float4(phi_f(q4.x), phi_f(q4.y), phi_f(q4.z), phi_f(q4.w));
        float4 kp = make_float4(phi_f(k4.x)*m, phi_f(k4.y)*m, phi_f(k4.z)*m, phi_f(k4.w)*m);
        kv.x = decay*kv.x + kp.x*v4.x*m; kv.y = decay*kv.y + kp.y*v4.y*m;
        kv.z = decay*kv.z + kp.z*v4.z*m; kv.w = decay*kv.w + kp.w*v4.w*m;
        ks.x = decay*ks.x + kp.x; ks.y = decay*ks.y + kp.y;
        ks.z = decay*ks.z + kp.z; ks.w = decay*ks.w + kp.w;
        float nl = qp.x*kv.x + qp.y*kv.y + qp.z*kv.z + qp.w*kv.w;
        float dl = qp.x*ks.x + qp.y*ks.y + qp.z*ks.z + qp.w*ks.w;
        float2 r = warp_red2(nl, dl);
        if (lane == 0) {
            int s = c * LCH_ + t;
            num_loc[(size_t)bh * S_ + s] = r.x;
            den_loc[(size_t)bh * S_ + s] = r.y;
        }
    }
    size_t sidx = ((size_t)bh * CH_ + c) * HD_ + lane * 4;
    *(float4*)(kv_loc + sidx) = kv;
    *(float4*)(ks_loc + sidx) = ks;
}

__global__ void __launch_bounds__(128) scan_phaseB(
    const float* __restrict__ kv0, const float* __restrict__ ks0,
    const float* __restrict__ decay_p,
    const float* __restrict__ kv_loc, const float* __restrict__ ks_loc,
    float* __restrict__ carry_kv, float* __restrict__ carry_ks,
    float* __restrict__ state_out, int write_states)
{
    const int bh = blockIdx.x;
    const int h  = bh % NH_;
    const int d  = threadIdx.x;
    const float decay = sigmoid_f(decay_p[h]);
    float dL = 1.f;
    #pragma unroll
    for (int i = 0; i < LCH_; i++) dL *= decay;
    float ckv = kv0[(size_t)bh * HD_ + d];
    float cks = ks0[(size_t)bh * HD_ + d];
    #pragma unroll
    for (int c = 0; c < CH_; c++) {
        size_t idx = ((size_t)bh * CH_ + c) * HD_ + d;
        carry_kv[idx] = ckv;
        carry_ks[idx] = cks;
        ckv = dL * ckv + kv_loc[idx];
        cks = dL * cks + ks_loc[idx];
    }
    if (write_states) {
        state_out[(size_t)bh * HD_ + d] = ckv;
        state_out[(size_t)(B_ * NH_ * HD_) + (size_t)bh * HD_ + d] = cks;
    }
}

// phase C: correction + output in fp16 (feeds single-product GEMM2)
__global__ void __launch_bounds__(128) scan_phaseC(
    const __half* __restrict__ qkv, const float* __restrict__ decay_p,
    const float* __restrict__ num_loc, const float* __restrict__ den_loc,
    const float* __restrict__ carry_kv, const float* __restrict__ carry_ks,
    __half* __restrict__ ah)
{
    const int gw = (blockIdx.x * blockDim.x + threadIdx.x) >> 5;
    const int lane = threadIdx.x & 31;
    const int c  = gw % CH_;
    const int bh = gw / CH_;
    const int h  = bh % NH_;
    const int b  = bh / NH_;
    const float decay = sigmoid_f(decay_p[h]);

    size_t sidx = ((size_t)bh * CH_ + c) * HD_ + lane * 4;
    const float4 ckv = *(const float4*)(carry_kv + sidx);
    const float4 cks = *(const float4*)(carry_ks + sidx);
    const size_t qbase = ((size_t)(b * S_ + c * LCH_)) * (3 * HID_) + h * HD_ + lane * 4;
    float dp = decay;

    for (int t = 0; t < LCH_; t++) {
        float4 q4 = load4h(qkv + qbase + (size_t)t * (3 * HID_));
        float4 qp = make_float4(phi_f(q4.x), phi_f(q4.y), phi_f(q4.z), phi_f(q4.w));
        float nl = qp.x*ckv.x + qp.y*ckv.y + qp.z*ckv.z + qp.w*ckv.w;
        float dl = qp.x*cks.x + qp.y*cks.y + qp.z*cks.z + qp.w*cks.w;
        float2 r = warp_red2(nl, dl);
        int s = c * LCH_ + t;
        float num = num_loc[(size_t)bh * S_ + s] + dp * r.x;
        float den = fmaxf(den_loc[(size_t)bh * S_ + s] + dp * r.y, 1e-6f);
        float sc = num / den;
        size_t oidx = ((size_t)(b * S_ + s)) * HID_ + h * HD_ + lane * 4;
        __half2 h01, h23;
        h01.x = __float2half_rn(sc * qp.x); h01.y = __float2half_rn(sc * qp.y);
        h23.x = __float2half_rn(sc * qp.z); h23.y = __float2half_rn(sc * qp.w);
        *(__half2*)(ah + oidx)     = h01;
        *(__half2*)(ah + oidx + 2) = h23;
        dp *= decay;
    }
}

// ---------------------------------------------------------------------------
// launch
// ---------------------------------------------------------------------------
extern "C" void kernel_launch(void* const* d_in, const int* in_sizes, int n_in,
                              void* d_out, int out_size)
{
    const float* x     = (const float*)d_in[0];
    const float* kv0   = (const float*)d_in[1];
    const float* ks0   = (const float*)d_in[2];
    const float* mask  = (const float*)d_in[3];
    const float* Wqkv  = (const float*)d_in[4];
    const float* Wout  = (const float*)d_in[5];
    const float* decay = (const float*)d_in[6];
    float* out = (float*)d_out;

    void* p;
    cudaGetSymbolAddress(&p, g_qkv);    __half* qkvbuf = (__half*)p;
    cudaGetSymbolAddress(&p, g_xh);     __half* xh = (__half*)p;
    cudaGetSymbolAddress(&p, g_ah);     __half* ah = (__half*)p;
    cudaGetSymbolAddress(&p, g_wqh);    __half* wqh = (__half*)p;
    cudaGetSymbolAddress(&p, g_woh);    __half* woh = (__half*)p;
    cudaGetSymbolAddress(&p, g_numloc); float* numloc = (float*)p;
    cudaGetSymbolAddress(&p, g_denloc); float* denloc = (float*)p;
    cudaGetSymbolAddress(&p, g_kvloc);  float* kvloc = (float*)p;
    cudaGetSymbolAddress(&p, g_ksloc);  float* ksloc = (float*)p;
    cudaGetSymbolAddress(&p, g_ckv);    float* ckv = (float*)p;
    cudaGetSymbolAddress(&p, g_cks);    float* cks = (float*)p;

    cudaFuncSetAttribute(gemm_main<__half>, cudaFuncAttributeMaxDynamicSharedMemorySize, MAIN_SMEM);
    cudaFuncSetAttribute(gemm_main<float>,  cudaFuncAttributeMaxDynamicSharedMemorySize, MAIN_SMEM);

    const size_t out_main = (size_t)M1_ * HID_;
    const int write_states = (out_size >= (int)(out_main + 2 * B_ * NH_ * HD_));
    float* state_out = out + out_main;

    // 1) conversions
    {
        int n4 = (M1_ * HID_) / 4;
        to_f16<<<(n4 + 255) / 256, 256>>>(x, xh, n4);
    }
    {
        dim3 blk(32, 8);
        dim3 g1(3 * HID_ / 32, HID_ / 32);
        trans_f16<<<g1, blk>>>(Wqkv, wqh, HID_, 3 * HID_);
        dim3 g2(HID_ / 32, HID_ / 32);
        trans_f16<<<g2, blk>>>(Wout, woh, HID_, HID_);
    }

    // 2) qkv = x @ W_qkv  (fp16 out)
    {
        dim3 grid(3 * HID_ / BN_, M1_ / BM_);
        gemm_main<__half><<<grid, 256, MAIN_SMEM>>>(xh, wqh, qkvbuf, 3 * HID_, HID_);
    }

    // 3) scan
    scan_phaseA<<<(B_ * NH_ * CH_) / 4, 128>>>(qkvbuf, mask, decay, numloc, denloc, kvloc, ksloc);
    scan_phaseB<<<B_ * NH_, HD_>>>(kv0, ks0, decay, kvloc, ksloc, ckv, cks,
                                   state_out, write_states);
    scan_phaseC<<<(B_ * NH_ * CH_) / 4, 128>>>(qkvbuf, decay, numloc, denloc, ckv, cks, ah);

    // 4) out = attn @ W_out  (fp32 out)
    {
        dim3 grid(HID_ / BN_, M1_ / BM_);
        gemm_main<float><<<grid, 256, MAIN_SMEM>>>(ah, woh, out, HID_, HID_);
    }
}

// round 11
// speedup vs baseline: 1.0654x; 1.0654x over previous
#include <cuda_runtime.h>
#include <cuda_fp16.h>
#include <math.h>
#include <stdint.h>

// Problem constants
#define B_   4
#define S_   2048
#define HID_ 2048
#define NH_  16
#define HD_  128
#define CH_  64
#define LCH_ 32
#define M1_  (B_*S_)   // 8192

// GEMM tiling (round-9 proven config: BK=32, swz64, 4-stage)
#define BM_ 128
#define BN_ 128
#define BK_ 32
#define MSTG_ 16384
#define MAIN_SMEM (4*MSTG_)      // 65536 -> 2 CTAs/SM

__device__ __forceinline__ uint32_t smem_to_u32(const void* p) {
    uint32_t a;
    asm("{ .reg .u64 t; cvta.to.shared.u64 t, %1; cvt.u32.u64 %0, t; }"
        : "=r"(a) : "l"(p));
    return a;
}
__device__ __forceinline__ uint32_t swz64(uint32_t b) { return b ^ ((b >> 3) & 0x30); }

#define CP_ASYNC16(sa, ga) \
    asm volatile("cp.async.cg.shared.global [%0], [%1], 16;" :: "r"((uint32_t)(sa)), "l"(ga))
#define CP_COMMIT() asm volatile("cp.async.commit_group;" ::: "memory")
#define CP_WAIT2()  asm volatile("cp.async.wait_group 2;" ::: "memory")

#define LDSM4(r, addr) \
    asm volatile("ldmatrix.sync.aligned.m8n8.x4.shared.b16 {%0,%1,%2,%3}, [%4];" \
        : "=r"((r)[0]), "=r"((r)[1]), "=r"((r)[2]), "=r"((r)[3]) : "r"(addr))

#define MMA_F32(c, a, b0, b1) \
    asm volatile("mma.sync.aligned.m16n8k16.row.col.f32.f16.f16.f32 " \
        "{%0,%1,%2,%3}, {%4,%5,%6,%7}, {%8,%9}, {%0,%1,%2,%3};" \
        : "+f"((c)[0]), "+f"((c)[1]), "+f"((c)[2]), "+f"((c)[3]) \
        : "r"((a)[0]), "r"((a)[1]), "r"((a)[2]), "r"((a)[3]), "r"(b0), "r"(b1))

// ---------------------------------------------------------------------------
// scratch
// ---------------------------------------------------------------------------
__device__ __half g_qkv[(size_t)M1_ * 3 * HID_];   // 96 MB fp16
__device__ __half g_xh[(size_t)M1_ * HID_];
__device__ __half g_ah[(size_t)M1_ * HID_];
__device__ __half g_wqh[(size_t)3 * HID_ * HID_];
__device__ __half g_woh[(size_t)HID_ * HID_];
__device__ float g_numloc[B_*NH_*S_];
__device__ float g_denloc[B_*NH_*S_];
__device__ float g_kvloc [B_*NH_*CH_*HD_];
__device__ float g_ksloc [B_*NH_*CH_*HD_];

// ---------------------------------------------------------------------------
// conversions
// ---------------------------------------------------------------------------
__global__ void __launch_bounds__(256) to_f16(
    const float* __restrict__ in, __half* __restrict__ outp, int n4)
{
    int i = blockIdx.x * blockDim.x + threadIdx.x;
    if (i >= n4) return;
    float4 v = ((const float4*)in)[i];
    __half2 a, b;
    a.x = __float2half_rn(v.x); a.y = __float2half_rn(v.y);
    b.x = __float2half_rn(v.z); b.y = __float2half_rn(v.w);
    ((__half2*)outp)[2*i]   = a;
    ((__half2*)outp)[2*i+1] = b;
}

// W[K,N] fp32 -> T[N,K] fp16
__global__ void __launch_bounds__(256) trans_f16(
    const float* __restrict__ W, __half* __restrict__ T, int K, int N)
{
    __shared__ float tile[32][33];
    int tx = threadIdx.x, ty = threadIdx.y;
    int bx = blockIdx.x * 32;  // N
    int by = blockIdx.y * 32;  // K
    #pragma unroll
    for (int j = 0; j < 4; j++)
        tile[ty + j*8][tx] = W[(size_t)(by + ty + j*8) * N + bx + tx];
    __syncthreads();
    #pragma unroll
    for (int j = 0; j < 4; j++) {
        float v = tile[tx][ty + j*8];
        T[(size_t)(bx + ty + j*8) * K + by + tx] = __float2half_rn(v);
    }
}

// ---------------------------------------------------------------------------
// GEMM: C[M,N] = A[M,K] * B[N,K]^T  (f16 in, f32 acc) — round-9 config
// ---------------------------------------------------------------------------
__device__ __forceinline__ void load_stage_main(
    uint32_t sb, int it, int m0, int n0, int K,
    const __half* __restrict__ A, const __half* __restrict__ Bv, int tid)
{
    uint32_t stg = sb + (uint32_t)(it & 3) * MSTG_;
    const int k0 = it * BK_;
    #pragma unroll
    for (int h = 0; h < 2; h++) {
        int n = tid + h * 256;
        int row = n >> 2, ch = n & 3;
        uint32_t so = swz64((uint32_t)(row * 64 + ch * 16));
        CP_ASYNC16(stg +        so, A  + (size_t)(m0 + row) * K + k0 + ch * 8);
        CP_ASYNC16(stg + 8192 + so, Bv + (size_t)(n0 + row) * K + k0 + ch * 8);
    }
}

template <typename OutT>
__global__ void __launch_bounds__(256, 2) gemm_main(
    const __half* __restrict__ Ah, const __half* __restrict__ Bh,
    OutT* __restrict__ C, int N, int K)
{
    extern __shared__ char smem[];
    uint32_t sb = smem_to_u32(smem);
    const int tid = threadIdx.x;
    const int lane = tid & 31;
    const int wid = tid >> 5;
    const int wm = wid & 1;
    const int wn = wid >> 1;

    const int m0 = blockIdx.y * BM_;
    const int n0 = blockIdx.x * BN_;
    const int nk = K / BK_;

    float acc[4][4][4];
    #pragma unroll
    for (int a = 0; a < 4; a++)
        #pragma unroll
        for (int b = 0; b < 4; b++)
            #pragma unroll
            for (int c = 0; c < 4; c++) acc[a][b][c] = 0.f;

    load_stage_main(sb, 0, m0, n0, K, Ah, Bh, tid); CP_COMMIT();
    load_stage_main(sb, 1, m0, n0, K, Ah, Bh, tid); CP_COMMIT();
    load_stage_main(sb, 2, m0, n0, K, Ah, Bh, tid); CP_COMMIT();

    const int aRow = wm * 64 + (lane & 15);
    const int aKh  = lane >> 4;
    const int bRow = wn * 32 + (lane & 7) + ((lane >> 4) << 3);
    const int bKh  = (lane >> 3) & 1;

    for (int i = 0; i < nk; i++) {
        CP_WAIT2();
        __syncthreads();
        uint32_t stg = sb + (uint32_t)(i & 3) * MSTG_;

        #pragma unroll
        for (int ks = 0; ks < 2; ks++) {
            uint32_t ah[4][4], bh[2][4];
            #pragma unroll
            for (int mt = 0; mt < 4; mt++) {
                uint32_t off = swz64((uint32_t)((aRow + mt * 16) * 64 + (ks * 2 + aKh) * 16));
                LDSM4(ah[mt], stg + off);
            }
            #pragma unroll
            for (int ng = 0; ng < 2; ng++) {
                uint32_t off = swz64((uint32_t)((bRow + ng * 16) * 64 + (ks * 2 + bKh) * 16));
                LDSM4(bh[ng], stg + 8192 + off);
            }
            #pragma unroll
            for (int mt = 0; mt < 4; mt++)
                #pragma unroll
                for (int nt = 0; nt < 4; nt++) {
                    const int ng = nt >> 1, p2 = (nt & 1) * 2;
                    MMA_F32(acc[mt][nt], ah[mt], bh[ng][p2], bh[ng][p2 + 1]);
                }
        }
        if (i + 3 < nk)
            load_stage_main(sb, i + 3, m0, n0, K, Ah, Bh, tid);
        CP_COMMIT();
    }

    const int rb = m0 + wm * 64 + (lane >> 2);
    const int cb = n0 + wn * 32 + (lane & 3) * 2;
    #pragma unroll
    for (int mt = 0; mt < 4; mt++) {
        #pragma unroll
        for (int nt = 0; nt < 4; nt++) {
            if constexpr (sizeof(OutT) == 4) {
                float* p0 = (float*)C + (size_t)(rb + mt * 16) * N + cb + nt * 8;
                float* p1 = (float*)C + (size_t)(rb + mt * 16 + 8) * N + cb + nt * 8;
                *(float2*)p0 = make_float2(acc[mt][nt][0], acc[mt][nt][1]);
                *(float2*)p1 = make_float2(acc[mt][nt][2], acc[mt][nt][3]);
            } else {
                __half* p0 = (__half*)C + (size_t)(rb + mt * 16) * N + cb + nt * 8;
                __half* p1 = (__half*)C + (size_t)(rb + mt * 16 + 8) * N + cb + nt * 8;
                __half2 v0, v1;
                v0.x = __float2half_rn(acc[mt][nt][0]); v0.y = __float2half_rn(acc[mt][nt][1]);
                v1.x = __float2half_rn(acc[mt][nt][2]); v1.y = __float2half_rn(acc[mt][nt][3]);
                *(__half2*)p0 = v0;
                *(__half2*)p1 = v1;
            }
        }
    }
}

// ---------------------------------------------------------------------------
// scan — warp-per-(bh,chunk); qkv in fp16; phaseB fused into phaseC
// ---------------------------------------------------------------------------
__device__ __forceinline__ float phi_f(float u) { return u > 0.f ? u + 1.f : expf(u); }
__device__ __forceinline__ float sigmoid_f(float p) { return 1.f / (1.f + expf(-p)); }

__device__ __forceinline__ float4 load4h(const __half* p) {
    uint2 raw = *(const uint2*)p;
    float2 a = __half22float2(*(__half2*)&raw.x);
    float2 b = __half22float2(*(__half2*)&raw.y);
    return make_float4(a.x, a.y, b.x, b.y);
}

__device__ __forceinline__ float2 warp_red2(float a, float b) {
    #pragma unroll
    for (int off = 16; off > 0; off >>= 1) {
        a += __shfl_xor_sync(0xffffffffu, a, off);
        b += __shfl_xor_sync(0xffffffffu, b, off);
    }
    return make_float2(a, b);
}

__global__ void __launch_bounds__(128) scan_phaseA(
    const __half* __restrict__ qkv, const float* __restrict__ mask,
    const float* __restrict__ decay_p,
    float* __restrict__ num_loc, float* __restrict__ den_loc,
    float* __restrict__ kv_loc, float* __restrict__ ks_loc)
{
    const int gw = (blockIdx.x * blockDim.x + threadIdx.x) >> 5;
    const int lane = threadIdx.x & 31;
    const int c  = gw % CH_;
    const int bh = gw / CH_;
    const int h  = bh % NH_;
    const int b  = bh / NH_;
    const float decay = sigmoid_f(decay_p[h]);

    float4 kv = make_float4(0,0,0,0), ks = make_float4(0,0,0,0);
    const size_t qbase = ((size_t)(b * S_ + c * LCH_)) * (3 * HID_) + h * HD_ + lane * 4;
    const float* mrow = mask + (size_t)b * S_ + c * LCH_;

    for (int t = 0; t < LCH_; t++) {
        size_t off = qbase + (size_t)t * (3 * HID_);
        float4 q4 = load4h(qkv + off);
        float4 k4 = load4h(qkv + off + HID_);
        float4 v4 = load4h(qkv + off + 2 * HID_);
        float m = mrow[t];
        float4 qp = make_float4(phi_f(q4.x), phi_f(q4.y), phi_f(q4.z), phi_f(q4.w));
        float4 kp = make_float4(phi_f(k4.x)*m, phi_f(k4.y)*m, phi_f(k4.z)*m, phi_f(k4.w)*m);
        kv.x = decay*kv.x + kp.x*v4.x*m; kv.y = decay*kv.y + kp.y*v4.y*m;
        kv.z = decay*kv.z + kp.z*v4.z*m; kv.w = decay*kv.w + kp.w*v4.w*m;
        ks.x = decay*ks.x + kp.x; ks.y = decay*ks.y + kp.y;
        ks.z = decay*ks.z + kp.z; ks.w = decay*ks.w + kp.w;
        float nl = qp.x*kv.x + qp.y*kv.y + qp.z*kv.z + qp.w*kv.w;
        float dl = qp.x*ks.x + qp.y*ks.y + qp.z*ks.z + qp.w*ks.w;
        float2 r = warp_red2(nl, dl);
        if (lane == 0) {
            int s = c * LCH_ + t;
            num_loc[(size_t)bh * S_ + s] = r.x;
            den_loc[(size_t)bh * S_ + s] = r.y;
        }
    }
    size_t sidx = ((size_t)bh * CH_ + c) * HD_ + lane * 4;
    *(float4*)(kv_loc + sidx) = kv;
    *(float4*)(ks_loc + sidx) = ks;
}

// phase C: inline carry prefix (fused phaseB) + correction + fp16 output.
// The c == CH_-1 warp also writes the final kv/ks states.
__global__ void __launch_bounds__(128) scan_phaseC(
    const __half* __restrict__ qkv, const float* __restrict__ decay_p,
    const float* __restrict__ num_loc, const float* __restrict__ den_loc,
    const float* __restrict__ kv_loc, const float* __restrict__ ks_loc,
    const float* __restrict__ kv0, const float* __restrict__ ks0,
    __half* __restrict__ ah,
    float* __restrict__ state_out, int write_states)
{
    const int gw = (blockIdx.x * blockDim.x + threadIdx.x) >> 5;
    const int lane = threadIdx.x & 31;
    const int c  = gw % CH_;
    const int bh = gw / CH_;
    const int h  = bh % NH_;
    const int b  = bh / NH_;
    const float decay = sigmoid_f(decay_p[h]);
    float dL = 1.f;
    #pragma unroll
    for (int i = 0; i < LCH_; i++) dL *= decay;

    // carry prefix over chunks c' < c (identical combine order to old phaseB)
    size_t base0 = (size_t)bh * HD_ + lane * 4;
    float4 ckv = *(const float4*)(kv0 + base0);
    float4 cks = *(const float4*)(ks0 + base0);
    for (int cp = 0; cp < c; cp++) {
        size_t idx = ((size_t)bh * CH_ + cp) * HD_ + lane * 4;
        float4 lkv = *(const float4*)(kv_loc + idx);
        float4 lks = *(const float4*)(ks_loc + idx);
        ckv.x = dL*ckv.x + lkv.x; ckv.y = dL*ckv.y + lkv.y;
        ckv.z = dL*ckv.z + lkv.z; ckv.w = dL*ckv.w + lkv.w;
        cks.x = dL*cks.x + lks.x; cks.y = dL*cks.y + lks.y;
        cks.z = dL*cks.z + lks.z; cks.w = dL*cks.w + lks.w;
    }
    if (write_states && c == CH_ - 1) {
        size_t idx = ((size_t)bh * CH_ + c) * HD_ + lane * 4;
        float4 lkv = *(const float4*)(kv_loc + idx);
        float4 lks = *(const float4*)(ks_loc + idx);
        float4 fkv = make_float4(dL*ckv.x + lkv.x, dL*ckv.y + lkv.y,
                                 dL*ckv.z + lkv.z, dL*ckv.w + lkv.w);
        float4 fks = make_float4(dL*cks.x + lks.x, dL*cks.y + lks.y,
                                 dL*cks.z + lks.z, dL*cks.w + lks.w);
        *(float4*)(state_out + base0) = fkv;
        *(float4*)(state_out + (size_t)(B_ * NH_ * HD_) + base0) = fks;
    }

    const size_t qbase = ((size_t)(b * S_ + c * LCH_)) * (3 * HID_) + h * HD_ + lane * 4;
    float dp = decay;

    for (int t = 0; t < LCH_; t++) {
        float4 q4 = load4h(qkv + qbase + (size_t)t * (3 * HID_));
        float4 qp = make_float4(phi_f(q4.x), phi_f(q4.y), phi_f(q4.z), phi_f(q4.w));
        float nl = qp.x*ckv.x + qp.y*ckv.y + qp.z*ckv.z + qp.w*ckv.w;
        float dl = qp.x*cks.x + qp.y*cks.y + qp.z*cks.z + qp.w*cks.w;
        float2 r = warp_red2(nl, dl);
        int s = c * LCH_ + t;
        float num = num_loc[(size_t)bh * S_ + s] + dp * r.x;
        float den = fmaxf(den_loc[(size_t)bh * S_ + s] + dp * r.y, 1e-6f);
        float sc = num / den;
        size_t oidx = ((size_t)(b * S_ + s)) * HID_ + h * HD_ + lane * 4;
        __half2 h01, h23;
        h01.x = __float2half_rn(sc * qp.x); h01.y = __float2half_rn(sc * qp.y);
        h23.x = __float2half_rn(sc * qp.z); h23.y = __float2half_rn(sc * qp.w);
        *(__half2*)(ah + oidx)     = h01;
        *(__half2*)(ah + oidx + 2) = h23;
        dp *= decay;
    }
}

// ---------------------------------------------------------------------------
// launch
// ---------------------------------------------------------------------------
extern "C" void kernel_launch(void* const* d_in, const int* in_sizes, int n_in,
                              void* d_out, int out_size)
{
    const float* x     = (const float*)d_in[0];
    const float* kv0   = (const float*)d_in[1];
    const float* ks0   = (const float*)d_in[2];
    const float* mask  = (const float*)d_in[3];
    const float* Wqkv  = (const float*)d_in[4];
    const float* Wout  = (const float*)d_in[5];
    const float* decay = (const float*)d_in[6];
    float* out = (float*)d_out;

    void* p;
    cudaGetSymbolAddress(&p, g_qkv);    __half* qkvbuf = (__half*)p;
    cudaGetSymbolAddress(&p, g_xh);     __half* xh = (__half*)p;
    cudaGetSymbolAddress(&p, g_ah);     __half* ah = (__half*)p;
    cudaGetSymbolAddress(&p, g_wqh);    __half* wqh = (__half*)p;
    cudaGetSymbolAddress(&p, g_woh);    __half* woh = (__half*)p;
    cudaGetSymbolAddress(&p, g_numloc); float* numloc = (float*)p;
    cudaGetSymbolAddress(&p, g_denloc); float* denloc = (float*)p;
    cudaGetSymbolAddress(&p, g_kvloc);  float* kvloc = (float*)p;
    cudaGetSymbolAddress(&p, g_ksloc);  float* ksloc = (float*)p;

    cudaFuncSetAttribute(gemm_main<__half>, cudaFuncAttributeMaxDynamicSharedMemorySize, MAIN_SMEM);
    cudaFuncSetAttribute(gemm_main<float>,  cudaFuncAttributeMaxDynamicSharedMemorySize, MAIN_SMEM);

    const size_t out_main = (size_t)M1_ * HID_;
    const int write_states = (out_size >= (int)(out_main + 2 * B_ * NH_ * HD_));
    float* state_out = out + out_main;

    // 1) conversions
    {
        int n4 = (M1_ * HID_) / 4;
        to_f16<<<(n4 + 255) / 256, 256>>>(x, xh, n4);
    }
    {
        dim3 blk(32, 8);
        dim3 g1(3 * HID_ / 32, HID_ / 32);
        trans_f16<<<g1, blk>>>(Wqkv, wqh, HID_, 3 * HID_);
        dim3 g2(HID_ / 32, HID_ / 32);
        trans_f16<<<g2, blk>>>(Wout, woh, HID_, HID_);
    }

    // 2) qkv = x @ W_qkv  (fp16 out)
    {
        dim3 grid(3 * HID_ / BN_, M1_ / BM_);
        gemm_main<__half><<<grid, 256, MAIN_SMEM>>>(xh, wqh, qkvbuf, 3 * HID_, HID_);
    }

    // 3) scan (phaseB fused into phaseC)
    scan_phaseA<<<(B_ * NH_ * CH_) / 4, 128>>>(qkvbuf, mask, decay, numloc, denloc, kvloc, ksloc);
    scan_phaseC<<<(B_ * NH_ * CH_) / 4, 128>>>(qkvbuf, decay, numloc, denloc,
                                               kvloc, ksloc, kv0, ks0, ah,
                                               state_out, write_states);

    // 4) out = attn @ W_out  (fp32 out)
    {
        dim3 grid(HID_ / BN_, M1_ / BM_);
        gemm_main<float><<<grid, 256, MAIN_SMEM>>>(ah, woh, out, HID_, HID_);
    }
}

// round 12
// speedup vs baseline: 1.0801x; 1.0138x over previous
#include <cuda_runtime.h>
#include <cuda_fp16.h>
#include <math.h>
#include <stdint.h>

// Problem constants
#define B_   4
#define S_   2048
#define HID_ 2048
#define NH_  16
#define HD_  128
#define CH_  64
#define LCH_ 32
#define M1_  (B_*S_)   // 8192

// GEMM tiling (round-9 proven config: BK=32, swz64, 4-stage)
#define BM_ 128
#define BN_ 128
#define BK_ 32
#define MSTG_ 16384
#define MAIN_SMEM (4*MSTG_)      // 65536 -> 2 CTAs/SM

__device__ __forceinline__ uint32_t smem_to_u32(const void* p) {
    uint32_t a;
    asm("{ .reg .u64 t; cvta.to.shared.u64 t, %1; cvt.u32.u64 %0, t; }"
        : "=r"(a) : "l"(p));
    return a;
}
__device__ __forceinline__ uint32_t swz64(uint32_t b) { return b ^ ((b >> 3) & 0x30); }

#define CP_ASYNC16(sa, ga) \
    asm volatile("cp.async.cg.shared.global [%0], [%1], 16;" :: "r"((uint32_t)(sa)), "l"(ga))
#define CP_COMMIT() asm volatile("cp.async.commit_group;" ::: "memory")
#define CP_WAIT2()  asm volatile("cp.async.wait_group 2;" ::: "memory")

#define LDSM4(r, addr) \
    asm volatile("ldmatrix.sync.aligned.m8n8.x4.shared.b16 {%0,%1,%2,%3}, [%4];" \
        : "=r"((r)[0]), "=r"((r)[1]), "=r"((r)[2]), "=r"((r)[3]) : "r"(addr))

#define MMA_F32(c, a, b0, b1) \
    asm volatile("mma.sync.aligned.m16n8k16.row.col.f32.f16.f16.f32 " \
        "{%0,%1,%2,%3}, {%4,%5,%6,%7}, {%8,%9}, {%0,%1,%2,%3};" \
        : "+f"((c)[0]), "+f"((c)[1]), "+f"((c)[2]), "+f"((c)[3]) \
        : "r"((a)[0]), "r"((a)[1]), "r"((a)[2]), "r"((a)[3]), "r"(b0), "r"(b1))

// ---------------------------------------------------------------------------
// scratch
// ---------------------------------------------------------------------------
__device__ __half g_qkv[(size_t)M1_ * 3 * HID_];   // 96 MB fp16
__device__ __half g_xh[(size_t)M1_ * HID_];
__device__ __half g_ah[(size_t)M1_ * HID_];
__device__ __half g_wqh[(size_t)3 * HID_ * HID_];
__device__ __half g_woh[(size_t)HID_ * HID_];
__device__ float g_numloc[B_*NH_*S_];
__device__ float g_denloc[B_*NH_*S_];
__device__ float g_kvloc [B_*NH_*CH_*HD_];
__device__ float g_ksloc [B_*NH_*CH_*HD_];
__device__ float g_ckv   [B_*NH_*CH_*HD_];
__device__ float g_cks   [B_*NH_*CH_*HD_];

// ---------------------------------------------------------------------------
// conversions
// ---------------------------------------------------------------------------
__global__ void __launch_bounds__(256) to_f16(
    const float* __restrict__ in, __half* __restrict__ outp, int n4)
{
    int i = blockIdx.x * blockDim.x + threadIdx.x;
    if (i >= n4) return;
    float4 v = ((const float4*)in)[i];
    __half2 a, b;
    a.x = __float2half_rn(v.x); a.y = __float2half_rn(v.y);
    b.x = __float2half_rn(v.z); b.y = __float2half_rn(v.w);
    ((__half2*)outp)[2*i]   = a;
    ((__half2*)outp)[2*i+1] = b;
}

// Both weight transposes in ONE launch.
// blockIdx.x in [0, 192): W_qkv [HID, 3*HID] -> wqh [3*HID, HID]
// blockIdx.x in [192,256): W_out [HID, HID]  -> woh [HID, HID]
__global__ void __launch_bounds__(256) trans_both(
    const float* __restrict__ Wqkv, __half* __restrict__ Tq,
    const float* __restrict__ Wout, __half* __restrict__ To)
{
    __shared__ float tile[32][33];
    int tx = threadIdx.x, ty = threadIdx.y;
    const int K = HID_;
    const float* W; __half* T; int N; int bxBlk;
    if (blockIdx.x < 192) { W = Wqkv; T = Tq; N = 3 * HID_; bxBlk = blockIdx.x; }
    else                  { W = Wout; T = To; N = HID_;     bxBlk = blockIdx.x - 192; }
    int bx = bxBlk * 32;        // N
    int by = blockIdx.y * 32;   // K
    #pragma unroll
    for (int j = 0; j < 4; j++)
        tile[ty + j*8][tx] = W[(size_t)(by + ty + j*8) * N + bx + tx];
    __syncthreads();
    #pragma unroll
    for (int j = 0; j < 4; j++) {
        float v = tile[tx][ty + j*8];
        T[(size_t)(bx + ty + j*8) * K + by + tx] = __float2half_rn(v);
    }
}

// ---------------------------------------------------------------------------
// GEMM: C[M,N] = A[M,K] * B[N,K]^T  (f16 in, f32 acc) — round-9 config
// ---------------------------------------------------------------------------
__device__ __forceinline__ void load_stage_main(
    uint32_t sb, int it, int m0, int n0, int K,
    const __half* __restrict__ A, const __half* __restrict__ Bv, int tid)
{
    uint32_t stg = sb + (uint32_t)(it & 3) * MSTG_;
    const int k0 = it * BK_;
    #pragma unroll
    for (int h = 0; h < 2; h++) {
        int n = tid + h * 256;
        int row = n >> 2, ch = n & 3;
        uint32_t so = swz64((uint32_t)(row * 64 + ch * 16));
        CP_ASYNC16(stg +        so, A  + (size_t)(m0 + row) * K + k0 + ch * 8);
        CP_ASYNC16(stg + 8192 + so, Bv + (size_t)(n0 + row) * K + k0 + ch * 8);
    }
}

template <typename OutT>
__global__ void __launch_bounds__(256, 2) gemm_main(
    const __half* __restrict__ Ah, const __half* __restrict__ Bh,
    OutT* __restrict__ C, int N, int K)
{
    extern __shared__ char smem[];
    uint32_t sb = smem_to_u32(smem);
    const int tid = threadIdx.x;
    const int lane = tid & 31;
    const int wid = tid >> 5;
    const int wm = wid & 1;
    const int wn = wid >> 1;

    const int m0 = blockIdx.y * BM_;
    const int n0 = blockIdx.x * BN_;
    const int nk = K / BK_;

    float acc[4][4][4];
    #pragma unroll
    for (int a = 0; a < 4; a++)
        #pragma unroll
        for (int b = 0; b < 4; b++)
            #pragma unroll
            for (int c = 0; c < 4; c++) acc[a][b][c] = 0.f;

    load_stage_main(sb, 0, m0, n0, K, Ah, Bh, tid); CP_COMMIT();
    load_stage_main(sb, 1, m0, n0, K, Ah, Bh, tid); CP_COMMIT();
    load_stage_main(sb, 2, m0, n0, K, Ah, Bh, tid); CP_COMMIT();

    const int aRow = wm * 64 + (lane & 15);
    const int aKh  = lane >> 4;
    const int bRow = wn * 32 + (lane & 7) + ((lane >> 4) << 3);
    const int bKh  = (lane >> 3) & 1;

    for (int i = 0; i < nk; i++) {
        CP_WAIT2();
        __syncthreads();
        uint32_t stg = sb + (uint32_t)(i & 3) * MSTG_;

        #pragma unroll
        for (int ks = 0; ks < 2; ks++) {
            uint32_t ah[4][4], bh[2][4];
            #pragma unroll
            for (int mt = 0; mt < 4; mt++) {
                uint32_t off = swz64((uint32_t)((aRow + mt * 16) * 64 + (ks * 2 + aKh) * 16));
                LDSM4(ah[mt], stg + off);
            }
            #pragma unroll
            for (int ng = 0; ng < 2; ng++) {
                uint32_t off = swz64((uint32_t)((bRow + ng * 16) * 64 + (ks * 2 + bKh) * 16));
                LDSM4(bh[ng], stg + 8192 + off);
            }
            #pragma unroll
            for (int mt = 0; mt < 4; mt++)
                #pragma unroll
                for (int nt = 0; nt < 4; nt++) {
                    const int ng = nt >> 1, p2 = (nt & 1) * 2;
                    MMA_F32(acc[mt][nt], ah[mt], bh[ng][p2], bh[ng][p2 + 1]);
                }
        }
        if (i + 3 < nk)
            load_stage_main(sb, i + 3, m0, n0, K, Ah, Bh, tid);
        CP_COMMIT();
    }

    const int rb = m0 + wm * 64 + (lane >> 2);
    const int cb = n0 + wn * 32 + (lane & 3) * 2;
    #pragma unroll
    for (int mt = 0; mt < 4; mt++) {
        #pragma unroll
        for (int nt = 0; nt < 4; nt++) {
            if constexpr (sizeof(OutT) == 4) {
                float* p0 = (float*)C + (size_t)(rb + mt * 16) * N + cb + nt * 8;
                float* p1 = (float*)C + (size_t)(rb + mt * 16 + 8) * N + cb + nt * 8;
                *(float2*)p0 = make_float2(acc[mt][nt][0], acc[mt][nt][1]);
                *(float2*)p1 = make_float2(acc[mt][nt][2], acc[mt][nt][3]);
            } else {
                __half* p0 = (__half*)C + (size_t)(rb + mt * 16) * N + cb + nt * 8;
                __half* p1 = (__half*)C + (size_t)(rb + mt * 16 + 8) * N + cb + nt * 8;
                __half2 v0, v1;
                v0.x = __float2half_rn(acc[mt][nt][0]); v0.y = __float2half_rn(acc[mt][nt][1]);
                v1.x = __float2half_rn(acc[mt][nt][2]); v1.y = __float2half_rn(acc[mt][nt][3]);
                *(__half2*)p0 = v0;
                *(__half2*)p1 = v1;
            }
        }
    }
}

// ---------------------------------------------------------------------------
// scan — warp-per-(bh,chunk); qkv in fp16 (round-9 structure)
// ---------------------------------------------------------------------------
__device__ __forceinline__ float phi_f(float u) { return u > 0.f ? u + 1.f : expf(u); }
__device__ __forceinline__ float sigmoid_f(float p) { return 1.f / (1.f + expf(-p)); }

__device__ __forceinline__ float4 load4h(const __half* p) {
    uint2 raw = *(const uint2*)p;
    float2 a = __half22float2(*(__half2*)&raw.x);
    float2 b = __half22float2(*(__half2*)&raw.y);
    return make_float4(a.x, a.y, b.x, b.y);
}

__device__ __forceinline__ float2 warp_red2(float a, float b) {
    #pragma unroll
    for (int off = 16; off > 0; off >>= 1) {
        a += __shfl_xor_sync(0xffffffffu, a, off);
        b += __shfl_xor_sync(0xffffffffu, b, off);
    }
    return make_float2(a, b);
}

__global__ void __launch_bounds__(128) scan_phaseA(
    const __half* __restrict__ qkv, const float* __restrict__ mask,
    const float* __restrict__ decay_p,
    float* __restrict__ num_loc, float* __restrict__ den_loc,
    float* __restrict__ kv_loc, float* __restrict__ ks_loc)
{
    const int gw = (blockIdx.x * blockDim.x + threadIdx.x) >> 5;
    const int lane = threadIdx.x & 31;
    const int c  = gw % CH_;
    const int bh = gw / CH_;
    const int h  = bh % NH_;
    const int b  = bh / NH_;
    const float decay = sigmoid_f(decay_p[h]);

    float4 kv = make_float4(0,0,0,0), ks = make_float4(0,0,0,0);
    const size_t qbase = ((size_t)(b * S_ + c * LCH_)) * (3 * HID_) + h * HD_ + lane * 4;
    const float* mrow = mask + (size_t)b * S_ + c * LCH_;

    for (int t = 0; t < LCH_; t++) {
        size_t off = qbase + (size_t)t * (3 * HID_);
        float4 q4 = load4h(qkv + off);
        float4 k4 = load4h(qkv + off + HID_);
        float4 v4 = load4h(qkv + off + 2 * HID_);
        float m = mrow[t];
        float4 qp = make_float4(phi_f(q4.x), phi_f(q4.y), phi_f(q4.z), phi_f(q4.w));
        float4 kp = make_float4(phi_f(k4.x)*m, phi_f(k4.y)*m, phi_f(k4.z)*m, phi_f(k4.w)*m);
        kv.x = decay*kv.x + kp.x*v4.x*m; kv.y = decay*kv.y + kp.y*v4.y*m;
        kv.z = decay*kv.z + kp.z*v4.z*m; kv.w = decay*kv.w + kp.w*v4.w*m;
        ks.x = decay*ks.x + kp.x; ks.y = decay*ks.y + kp.y;
        ks.z = decay*ks.z + kp.z; ks.w = decay*ks.w + kp.w;
        float nl = qp.x*kv.x + qp.y*kv.y + qp.z*kv.z + qp.w*kv.w;
        float dl = qp.x*ks.x + qp.y*ks.y + qp.z*ks.z + qp.w*ks.w;
        float2 r = warp_red2(nl, dl);
        if (lane == 0) {
            int s = c * LCH_ + t;
            num_loc[(size_t)bh * S_ + s] = r.x;
            den_loc[(size_t)bh * S_ + s] = r.y;
        }
    }
    size_t sidx = ((size_t)bh * CH_ + c) * HD_ + lane * 4;
    *(float4*)(kv_loc + sidx) = kv;
    *(float4*)(ks_loc + sidx) = ks;
}

__global__ void __launch_bounds__(128) scan_phaseB(
    const float* __restrict__ kv0, const float* __restrict__ ks0,
    const float* __restrict__ decay_p,
    const float* __restrict__ kv_loc, const float* __restrict__ ks_loc,
    float* __restrict__ carry_kv, float* __restrict__ carry_ks,
    float* __restrict__ state_out, int write_states)
{
    const int bh = blockIdx.x;
    const int h  = bh % NH_;
    const int d  = threadIdx.x;
    const float decay = sigmoid_f(decay_p[h]);
    float dL = 1.f;
    #pragma unroll
    for (int i = 0; i < LCH_; i++) dL *= decay;
    float ckv = kv0[(size_t)bh * HD_ + d];
    float cks = ks0[(size_t)bh * HD_ + d];
    #pragma unroll
    for (int c = 0; c < CH_; c++) {
        size_t idx = ((size_t)bh * CH_ + c) * HD_ + d;
        carry_kv[idx] = ckv;
        carry_ks[idx] = cks;
        ckv = dL * ckv + kv_loc[idx];
        cks = dL * cks + ks_loc[idx];
    }
    if (write_states) {
        state_out[(size_t)bh * HD_ + d] = ckv;
        state_out[(size_t)(B_ * NH_ * HD_) + (size_t)bh * HD_ + d] = cks;
    }
}

// phase C: correction + output in fp16 (feeds single-product GEMM2)
__global__ void __launch_bounds__(128) scan_phaseC(
    const __half* __restrict__ qkv, const float* __restrict__ decay_p,
    const float* __restrict__ num_loc, const float* __restrict__ den_loc,
    const float* __restrict__ carry_kv, const float* __restrict__ carry_ks,
    __half* __restrict__ ah)
{
    const int gw = (blockIdx.x * blockDim.x + threadIdx.x) >> 5;
    const int lane = threadIdx.x & 31;
    const int c  = gw % CH_;
    const int bh = gw / CH_;
    const int h  = bh % NH_;
    const int b  = bh / NH_;
    const float decay = sigmoid_f(decay_p[h]);

    size_t sidx = ((size_t)bh * CH_ + c) * HD_ + lane * 4;
    const float4 ckv = *(const float4*)(carry_kv + sidx);
    const float4 cks = *(const float4*)(carry_ks + sidx);
    const size_t qbase = ((size_t)(b * S_ + c * LCH_)) * (3 * HID_) + h * HD_ + lane * 4;
    float dp = decay;

    for (int t = 0; t < LCH_; t++) {
        float4 q4 = load4h(qkv + qbase + (size_t)t * (3 * HID_));
        float4 qp = make_float4(phi_f(q4.x), phi_f(q4.y), phi_f(q4.z), phi_f(q4.w));
        float nl = qp.x*ckv.x + qp.y*ckv.y + qp.z*ckv.z + qp.w*ckv.w;
        float dl = qp.x*cks.x + qp.y*cks.y + qp.z*cks.z + qp.w*cks.w;
        float2 r = warp_red2(nl, dl);
        int s = c * LCH_ + t;
        float num = num_loc[(size_t)bh * S_ + s] + dp * r.x;
        float den = fmaxf(den_loc[(size_t)bh * S_ + s] + dp * r.y, 1e-6f);
        float sc = num / den;
        size_t oidx = ((size_t)(b * S_ + s)) * HID_ + h * HD_ + lane * 4;
        __half2 h01, h23;
        h01.x = __float2half_rn(sc * qp.x); h01.y = __float2half_rn(sc * qp.y);
        h23.x = __float2half_rn(sc * qp.z); h23.y = __float2half_rn(sc * qp.w);
        *(__half2*)(ah + oidx)     = h01;
        *(__half2*)(ah + oidx + 2) = h23;
        dp *= decay;
    }
}

// ---------------------------------------------------------------------------
// launch
// ---------------------------------------------------------------------------
extern "C" void kernel_launch(void* const* d_in, const int* in_sizes, int n_in,
                              void* d_out, int out_size)
{
    const float* x     = (const float*)d_in[0];
    const float* kv0   = (const float*)d_in[1];
    const float* ks0   = (const float*)d_in[2];
    const float* mask  = (const float*)d_in[3];
    const float* Wqkv  = (const float*)d_in[4];
    const float* Wout  = (const float*)d_in[5];
    const float* decay = (const float*)d_in[6];
    float* out = (float*)d_out;

    void* p;
    cudaGetSymbolAddress(&p, g_qkv);    __half* qkvbuf = (__half*)p;
    cudaGetSymbolAddress(&p, g_xh);     __half* xh = (__half*)p;
    cudaGetSymbolAddress(&p, g_ah);     __half* ah = (__half*)p;
    cudaGetSymbolAddress(&p, g_wqh);    __half* wqh = (__half*)p;
    cudaGetSymbolAddress(&p, g_woh);    __half* woh = (__half*)p;
    cudaGetSymbolAddress(&p, g_numloc); float* numloc = (float*)p;
    cudaGetSymbolAddress(&p, g_denloc); float* denloc = (float*)p;
    cudaGetSymbolAddress(&p, g_kvloc);  float* kvloc = (float*)p;
    cudaGetSymbolAddress(&p, g_ksloc);  float* ksloc = (float*)p;
    cudaGetSymbolAddress(&p, g_ckv);    float* ckv = (float*)p;
    cudaGetSymbolAddress(&p, g_cks);    float* cks = (float*)p;

    cudaFuncSetAttribute(gemm_main<__half>, cudaFuncAttributeMaxDynamicSharedMemorySize, MAIN_SMEM);
    cudaFuncSetAttribute(gemm_main<float>,  cudaFuncAttributeMaxDynamicSharedMemorySize, MAIN_SMEM);

    const size_t out_main = (size_t)M1_ * HID_;
    const int write_states = (out_size >= (int)(out_main + 2 * B_ * NH_ * HD_));
    float* state_out = out + out_main;

    // 1) conversions: x -> fp16; both weight transposes in ONE launch
    {
        int n4 = (M1_ * HID_) / 4;
        to_f16<<<(n4 + 255) / 256, 256>>>(x, xh, n4);
    }
    {
        dim3 blk(32, 8);
        dim3 g(256, HID_ / 32);   // 192 col-tiles Wqkv + 64 col-tiles Wout
        trans_both<<<g, blk>>>(Wqkv, wqh, Wout, woh);
    }

    // 2) qkv = x @ W_qkv  (fp16 out)
    {
        dim3 grid(3 * HID_ / BN_, M1_ / BM_);
        gemm_main<__half><<<grid, 256, MAIN_SMEM>>>(xh, wqh, qkvbuf, 3 * HID_, HID_);
    }

    // 3) scan (round-9 structure: A, B, C)
    scan_phaseA<<<(B_ * NH_ * CH_) / 4, 128>>>(qkvbuf, mask, decay, numloc, denloc, kvloc, ksloc);
    scan_phaseB<<<B_ * NH_, HD_>>>(kv0, ks0, decay, kvloc, ksloc, ckv, cks,
                                   state_out, write_states);
    scan_phaseC<<<(B_ * NH_ * CH_) / 4, 128>>>(qkvbuf, decay, numloc, denloc, ckv, cks, ah);

    // 4) out = attn @ W_out  (fp32 out)
    {
        dim3 grid(HID_ / BN_, M1_ / BM_);
        gemm_main<float><<<grid, 256, MAIN_SMEM>>>(ah, woh, out, HID_, HID_);
    }
}